// round 16
// baseline (speedup 1.0000x reference)
#include <cuda_runtime.h>
#include <cuda_bf16.h>
#include <cuda_fp16.h>
#include <math.h>
#include <cstdint>

#define B 128
#define S 1024
#define H 256
#define V 256

// Scratch (device globals: allocation-free rule)
__device__ __half g_hhi[(size_t)B * S * H];   // hidden states, fp16 hi
__device__ float g_table[V * H];
__device__ float g_context[B * H];
__device__ int   g_is64;
__device__ __half g_wah[H * H];   // Wattn fp16
__device__ __half g_wfh[V * H];   // Wfc   fp16

typedef unsigned long long ull;

#define SWZ(o) ((o) ^ (((o) >> 3) & 0x70))

// ---- packed f32x2 helpers (k_rnn) ------------------------------------------
__device__ __forceinline__ ull fma2(ull a, ull b, ull c) {
    ull d;
    asm("fma.rn.f32x2 %0, %1, %2, %3;" : "=l"(d) : "l"(a), "l"(b), "l"(c));
    return d;
}
__device__ __forceinline__ float2 unpk(ull v) {
    float2 r;
    asm("mov.b64 {%0, %1}, %2;" : "=f"(r.x), "=f"(r.y) : "l"(v));
    return r;
}
__device__ __forceinline__ float tanhfast(float x) {
    float y;
    asm("tanh.approx.f32 %0, %1;" : "=f"(y) : "f"(x));
    return y;
}
__device__ __forceinline__ float hsum2(ull a, ull b) {
    float2 u = unpk(a), v = unpk(b);
    return (u.x + u.y) + (v.x + v.y);
}
__device__ __forceinline__ uint32_t smem_u32(const void* p) {
    uint32_t a;
    asm("{ .reg .u64 t; cvta.to.shared.u64 t, %1; cvt.u32.u64 %0, t; }"
        : "=r"(a) : "l"(p));
    return a;
}

// ---- sm80-class tensor ops --------------------------------------------------
#define LDSM4(r, a)                                                           \
    asm volatile("ldmatrix.sync.aligned.m8n8.x4.shared.b16 {%0,%1,%2,%3}, [%4];" \
        : "=r"((r)[0]), "=r"((r)[1]), "=r"((r)[2]), "=r"((r)[3]) : "r"(a))

#define MMA(d, a, bb)                                                         \
    asm volatile("mma.sync.aligned.m16n8k16.row.col.f32.f16.f16.f32 "         \
        "{%0,%1,%2,%3},{%4,%5,%6,%7},{%8,%9},{%0,%1,%2,%3};"                  \
        : "+f"((d)[0]), "+f"((d)[1]), "+f"((d)[2]), "+f"((d)[3])              \
        : "r"((a)[0]), "r"((a)[1]), "r"((a)[2]), "r"((a)[3]),                 \
          "r"((bb)[0]), "r"((bb)[1]))

// ---------------------------------------------------------------------------
// K0: detect int64 vs int32 tokens
// ---------------------------------------------------------------------------
__global__ void k_detect(const unsigned int* __restrict__ xw) {
    __shared__ unsigned int red[32];
    unsigned int acc = 0;
    int tid = threadIdx.x;
    for (int i = tid; i < (B * S) / 2; i += 1024) acc |= xw[2 * i + 1];
    #pragma unroll
    for (int o = 16; o; o >>= 1) acc |= __shfl_xor_sync(0xffffffffu, acc, o);
    if ((tid & 31) == 0) red[tid >> 5] = acc;
    __syncthreads();
    if (tid == 0) {
        unsigned int a = 0;
        #pragma unroll
        for (int w = 0; w < 32; w++) a |= red[w];
        g_is64 = (a == 0) ? 1 : 0;
    }
}

// ---------------------------------------------------------------------------
// K1: table[v][j] = bxh[j] + bhh[j] + embed[v,:]·Wxh[j,:]
//     + fused fp32->fp16 conversion of Wattn/Wfc (same index space).
// ---------------------------------------------------------------------------
__global__ void k_table(const float* __restrict__ embed,
                        const float* __restrict__ Wxh,
                        const float* __restrict__ bxh,
                        const float* __restrict__ bhh,
                        const float* __restrict__ Wa,
                        const float* __restrict__ Wf,
                        __half* __restrict__ ha, __half* __restrict__ hf) {
    int v = blockIdx.x, j = threadIdx.x;
    int i = v * 256 + j;
    ha[i] = __float2half_rn(Wa[i]);
    hf[i] = __float2half_rn(Wf[i]);

    __shared__ float es[H];
    es[j] = embed[v * H + j];
    __syncthreads();
    float a0 = bxh[j] + bhh[j], a1 = 0.f, a2 = 0.f, a3 = 0.f;
    const float4* w4 = (const float4*)(Wxh + j * H);
    const float4* e4 = (const float4*)es;
    #pragma unroll
    for (int k = 0; k < H / 4; k++) {
        float4 w = w4[k], e = e4[k];
        a0 += w.x * e.x; a1 += w.y * e.y; a2 += w.z * e.z; a3 += w.w * e.w;
    }
    g_table[v * H + j] = (a0 + a1) + (a2 + a3);
}

// ---------------------------------------------------------------------------
// K2: Elman recurrence — frozen proven design; stores fp16-hi only.
// ---------------------------------------------------------------------------
#define KREG 192
#define KSMG 16
#define SMEM_RNN (KSMG * 256 * 16 + 2 * 256 * 4)

__global__ void __launch_bounds__(256, 1)
k_rnn(const void* __restrict__ xraw, const float* __restrict__ Whh) {
    extern __shared__ char smraw[];
    ulonglong2* ws = (ulonglong2*)smraw;
    float* hsm = (float*)(smraw + KSMG * 256 * 16);

    int tid = threadIdx.x, b = blockIdx.x;

    for (int i = tid; i < KSMG * 256; i += 256) {
        int j = i & 255, g = i >> 8;
        ws[i] = *(const ulonglong2*)(Whh + j * H + KREG + 4 * g);
    }
    ull w[96];
    {
        const ulonglong2* p = (const ulonglong2*)(Whh + tid * H);
        #pragma unroll
        for (int i = 0; i < 48; i++) {
            ulonglong2 v = p[i];
            w[2 * i] = v.x; w[2 * i + 1] = v.y;
        }
    }
    hsm[tid] = 0.f;

    int is64 = g_is64;
    const long long* x64 = (const long long*)xraw;
    const int*       x32 = (const int*)xraw;
    __syncthreads();

    int tok0 = is64 ? (int)x64[(size_t)b * S] : x32[b * S];
    float tv = g_table[tok0 * H + tid];
    int tokn = is64 ? (int)x64[(size_t)b * S + 1] : x32[b * S + 1];
    __half* hp = g_hhi + (size_t)b * S * H + tid;

    for (int t = 0; t < S; t++) {
        float tvn = (t + 1 < S) ? g_table[tokn * H + tid] : 0.f;
        int tokn2 = (t + 2 < S)
                    ? (is64 ? (int)x64[(size_t)b * S + t + 2] : x32[b * S + t + 2])
                    : 0;

        const ulonglong2* h2 = (const ulonglong2*)(hsm + ((t & 1) << 8));
        ull a0 = 0ull, a1 = 0ull, a2 = 0ull, a3 = 0ull;
        #pragma unroll
        for (int i = 0; i < 48; i++) {
            ulonglong2 hh = h2[i];
            a0 = fma2(w[2 * i],     hh.x, a0);
            a1 = fma2(w[2 * i + 1], hh.y, a1);
        }
        #pragma unroll
        for (int g = 0; g < KSMG; g++) {
            ulonglong2 hv = h2[48 + g];
            ulonglong2 wv = ws[(g << 8) + tid];
            a2 = fma2(wv.x, hv.x, a2);
            a3 = fma2(wv.y, hv.y, a3);
        }
        float s = hsum2(a0, a1) + hsum2(a2, a3) + tv;
        float hn = tanhfast(s);

        hsm[(((t & 1) ^ 1) << 8) + tid] = hn;
        hp[(size_t)t * H] = __float2half_rn(hn);
        tv = tvn; tokn = tokn2;
        __syncthreads();
    }
}

// ---------------------------------------------------------------------------
// HMMA GEMM (single-pass fp16). CTA = 128 rows x 128 s, K=256, 8 warps.
// SMEM: A [0,64K): 4 chunks x [128 rows][64 k] SW128 fp16.
//       B at 64K: FOUR buffers x 16KB (whole s-block resident).
//       score buffer at 128K: [128 s][132] fp32.
// ---------------------------------------------------------------------------
#define SMB 65536
#define SMBUF 16384
#define SMSC 131072
#define SCPITCH 132
#define SMEM_TC (SMSC + 128 * SCPITCH * 4)   // 198656

__device__ __forceinline__ void stage_A(char* smA,
                                        const __half* __restrict__ W,
                                        int tid) {
    #pragma unroll
    for (int it = 0; it < 16; it++) {
        int idx = it * 256 + tid;
        int j = idx >> 5, kg = idx & 31;
        uint4 v = *(const uint4*)(W + ((size_t)j << 8) + (kg << 3));
        int c = kg >> 3;
        int kb = (kg & 7) << 4;
        *(uint4*)(smA + c * 16384 + SWZ(j * 128 + kb)) = v;
    }
}

__device__ __forceinline__ void ldgB(uint4* v, const __half* __restrict__ rb,
                                     int tid) {
    int s = tid >> 1, hf = tid & 1;
    const uint4* src = (const uint4*)(rb + (size_t)s * H + hf * 32);
    #pragma unroll
    for (int i = 0; i < 4; i++) v[i] = src[i];
}
__device__ __forceinline__ void stsB(char* smB, const uint4* v, int tid) {
    int s = tid >> 1, hf = tid & 1;
    #pragma unroll
    for (int i = 0; i < 4; i++)
        *(uint4*)(smB + SWZ(s * 128 + hf * 64 + i * 16)) = v[i];
}

__device__ __forceinline__ void mma_chunk(float* acc, uint32_t aB, uint32_t bB,
                                          int cchunk, int wj, int ws, int lane) {
    int r = lane & 7, g = lane >> 3;
    #pragma unroll
    for (int kt = 0; kt < 4; kt++) {
        unsigned ah[2][4];
        #pragma unroll
        for (int mt = 0; mt < 2; mt++) {
            int row = wj * 32 + mt * 16 + (g & 1) * 8 + r;
            LDSM4(ah[mt], aB + cchunk * 16384 +
                          SWZ(row * 128 + kt * 32 + (g >> 1) * 16));
        }
        unsigned bh[4][4];
        #pragma unroll
        for (int pr = 0; pr < 4; pr++) {
            int srow = ws * 64 + pr * 16 + (g >> 1) * 8 + r;
            LDSM4(bh[pr], bB + SWZ(srow * 128 + kt * 32 + (g & 1) * 16));
        }
        #pragma unroll
        for (int mt = 0; mt < 2; mt++)
            #pragma unroll
            for (int nt = 0; nt < 8; nt++) {
                float* d = acc + (mt * 8 + nt) * 4;
                unsigned* bhp = &bh[nt >> 1][(nt & 1) * 2];
                MMA(d, ah[mt], bhp);
            }
    }
}

__device__ __forceinline__ void stage_scores(float* scs, const float* acc,
                                             int wj, int ws, int mrow, int c2) {
    #pragma unroll
    for (int mt = 0; mt < 2; mt++)
        #pragma unroll
        for (int nt = 0; nt < 8; nt++)
            #pragma unroll
            for (int rr = 0; rr < 2; rr++)
                #pragma unroll
                for (int col = 0; col < 2; col++)
                    scs[(ws * 64 + nt * 8 + c2 + col) * SCPITCH +
                        wj * 32 + mt * 16 + rr * 8 + mrow] =
                        acc[(mt * 8 + nt) * 4 + 2 * rr + col];
}

// ---------------------------------------------------------------------------
// K3: scores GEMM + no-max softmax + context. Grid (2, B), 256 thr, occ 1.
// Trimmed barriers: 1 sync/iter except epilogue iters.
// ---------------------------------------------------------------------------
__global__ void __launch_bounds__(256, 1)
k_attn(const float* __restrict__ battn) {
    extern __shared__ char sm[];
    uint32_t sb = smem_u32(sm);
    float* scs = (float*)(sm + SMSC);
    int tid = threadIdx.x, lane = tid & 31, w = tid >> 5;
    int wj = w >> 1, ws = w & 1;
    int mrow = lane >> 2, c2 = (lane & 3) * 2;
    int b = blockIdx.y, jt = blockIdx.x, jbase = jt * 128;

    stage_A(sm, g_wah + (size_t)jbase * H, tid);

    const __half* hhi = g_hhi + (size_t)b * S * H;

    int jq = tid & 31, sq = tid >> 5;
    float4 bb4 = *(const float4*)(battn + jbase + jq * 4);
    int bufc = jt * 2 + (jq >> 4);
    int kloc8 = (jq & 15) * 8;
    float li[4] = {0.f, 0.f, 0.f, 0.f};
    float ci[4] = {0.f, 0.f, 0.f, 0.f};

    float acc[64];
    #pragma unroll
    for (int i = 0; i < 64; i++) acc[i] = 0.f;

    {
        uint4 v0[4];
        ldgB(v0, hhi, tid);
        stsB(sm + SMB, v0, tid);
    }
    __syncthreads();

    for (int q = 0; q < 32; q++) {
        uint4 nv[4];
        if (q < 31)
            ldgB(nv, hhi + (size_t)((q + 1) >> 2) * 128 * H + ((q + 1) & 3) * 64,
                 tid);
        mma_chunk(acc, sb, sb + SMB + (q & 3) * SMBUF, q & 3, wj, ws, lane);

        if ((q & 3) == 3) {
            stage_scores(scs, acc, wj, ws, mrow, c2);
            __syncthreads();
            #pragma unroll
            for (int ss = 0; ss < 16; ss++) {
                int sl = sq * 16 + ss;
                float4 sv = *(const float4*)(scs + sl * SCPITCH + jq * 4);
                ull hraw = *(const ull*)(sm + SMB + bufc * SMBUF +
                                         SWZ(sl * 128 + kloc8));
                __half2 hA = *(__half2*)&hraw;
                __half2 hB = *((__half2*)&hraw + 1);
                float2 f01 = __half22float2(hA);
                float2 f23 = __half22float2(hB);
                float p0 = __expf(sv.x + bb4.x);
                float p1 = __expf(sv.y + bb4.y);
                float p2 = __expf(sv.z + bb4.z);
                float p3 = __expf(sv.w + bb4.w);
                li[0] += p0; ci[0] += p0 * f01.x;
                li[1] += p1; ci[1] += p1 * f01.y;
                li[2] += p2; ci[2] += p2 * f23.x;
                li[3] += p3; ci[3] += p3 * f23.y;
            }
            #pragma unroll
            for (int i = 0; i < 64; i++) acc[i] = 0.f;
            __syncthreads();   // epilogue reads (scs + all 4 bufs) done
        }
        if (q < 31)
            stsB(sm + SMB + ((q + 1) & 3) * SMBUF, nv, tid);
        __syncthreads();       // stores visible for next iter's mma
    }

    float* Ml = scs;
    float* Mc = scs + 128 * 9;
    #pragma unroll
    for (int c = 0; c < 4; c++) {
        Ml[(jq * 4 + c) * 9 + sq] = li[c];
        Mc[(jq * 4 + c) * 9 + sq] = ci[c];
    }
    __syncthreads();
    if (tid < 128) {
        float L = 0.f, C = 0.f;
        #pragma unroll
        for (int p = 0; p < 8; p++) {
            L += Ml[tid * 9 + p];
            C += Mc[tid * 9 + p];
        }
        g_context[b * H + jbase + tid] = C / L;
    }
}

// ---------------------------------------------------------------------------
// K4: output GEMM. Grid (2, B), 256 thr, occ 1. Computes its own ctxout
// slice in the prologue (absorbs former k_ctxout). Coalesced STG.128.
// ---------------------------------------------------------------------------
__global__ void __launch_bounds__(256, 1)
k_out(const float* __restrict__ Wfc, const float* __restrict__ bfc,
      float* __restrict__ out) {
    extern __shared__ char sm[];
    uint32_t sb = smem_u32(sm);
    float* scs = (float*)(sm + SMSC);
    int tid = threadIdx.x, lane = tid & 31, w = tid >> 5;
    int wj = w >> 1, ws = w & 1;
    int mrow = lane >> 2, c2 = (lane & 3) * 2;
    int b = blockIdx.y, vbase = blockIdx.x * 128;

    stage_A(sm, g_wfh + (size_t)vbase * H, tid);

    const __half* hhi = g_hhi + (size_t)b * S * H;
    float* ob = out + (size_t)b * S * V;
    int vq = tid & 31, sq = tid >> 5;

    // ---- prologue: compute ctxout for this CTA's 128 v (uses scs scratch) --
    float* ctx  = scs;          // 256
    float* psum = scs + 256;    // 256
    float* ctxo = scs + 512;    // 128
    ctx[tid] = g_context[b * H + tid];
    __syncthreads();
    {
        int vloc = tid >> 1, hf = tid & 1;
        const float4* wr = (const float4*)(Wfc + (size_t)(vbase + vloc) * H +
                                           hf * 128);
        const float4* c4 = (const float4*)(ctx + hf * 128);
        float a0 = 0.f, a1 = 0.f, a2 = 0.f, a3 = 0.f;
        #pragma unroll
        for (int i = 0; i < 32; i++) {
            float4 ww = wr[i], cc = c4[i];
            a0 += ww.x * cc.x; a1 += ww.y * cc.y;
            a2 += ww.z * cc.z; a3 += ww.w * cc.w;
        }
        psum[tid] = (a0 + a1) + (a2 + a3);
    }
    __syncthreads();
    if (tid < 128) ctxo[tid] = bfc[vbase + tid] + psum[2 * tid] + psum[2 * tid + 1];
    __syncthreads();
    float4 cv4 = make_float4(ctxo[vq * 4], ctxo[vq * 4 + 1],
                             ctxo[vq * 4 + 2], ctxo[vq * 4 + 3]);
    __syncthreads();

    float acc[64];
    #pragma unroll
    for (int i = 0; i < 64; i++) acc[i] = 0.f;

    {
        uint4 v0[4];
        ldgB(v0, hhi, tid);
        stsB(sm + SMB, v0, tid);
    }
    __syncthreads();

    for (int q = 0; q < 32; q++) {
        uint4 nv[4];
        if (q < 31)
            ldgB(nv, hhi + (size_t)((q + 1) >> 2) * 128 * H + ((q + 1) & 3) * 64,
                 tid);
        mma_chunk(acc, sb, sb + SMB + (q & 3) * SMBUF, q & 3, wj, ws, lane);

        if ((q & 3) == 3) {
            int sch = q >> 2;
            stage_scores(scs, acc, wj, ws, mrow, c2);
            __syncthreads();
            #pragma unroll
            for (int ss = 0; ss < 16; ss++) {
                int sl = sq * 16 + ss;
                int sg = sch * 128 + sl;
                float4 dv = *(const float4*)(scs + sl * SCPITCH + vq * 4);
                dv.x += cv4.x; dv.y += cv4.y; dv.z += cv4.z; dv.w += cv4.w;
                *(float4*)(ob + (size_t)sg * V + vbase + vq * 4) = dv;
            }
            #pragma unroll
            for (int i = 0; i < 64; i++) acc[i] = 0.f;
            __syncthreads();
        }
        if (q < 31)
            stsB(sm + SMB + ((q + 1) & 3) * SMBUF, nv, tid);
        __syncthreads();
    }
}

// ---------------------------------------------------------------------------
extern "C" void kernel_launch(void* const* d_in, const int* in_sizes, int n_in,
                              void* d_out, int out_size) {
    const void*  x     = d_in[0];
    const float* embed = (const float*)d_in[1];
    const float* Wxh   = (const float*)d_in[2];
    const float* bxh   = (const float*)d_in[3];
    const float* Whh   = (const float*)d_in[4];
    const float* bhh   = (const float*)d_in[5];
    const float* Wattn = (const float*)d_in[6];
    const float* battn = (const float*)d_in[7];
    const float* Wfc   = (const float*)d_in[8];
    const float* bfc   = (const float*)d_in[9];
    float* out = (float*)d_out;

    cudaFuncSetAttribute(k_rnn, cudaFuncAttributeMaxDynamicSharedMemorySize,
                         SMEM_RNN);
    cudaFuncSetAttribute(k_attn, cudaFuncAttributeMaxDynamicSharedMemorySize,
                         SMEM_TC);
    cudaFuncSetAttribute(k_out, cudaFuncAttributeMaxDynamicSharedMemorySize,
                         SMEM_TC);

    __half *wah, *wfh;
    cudaGetSymbolAddress((void**)&wah, g_wah);
    cudaGetSymbolAddress((void**)&wfh, g_wfh);

    k_detect<<<1, 1024>>>((const unsigned int*)x);
    k_table<<<V, H>>>(embed, Wxh, bxh, bhh, Wattn, Wfc, wah, wfh);
    k_rnn<<<B, 256, SMEM_RNN>>>(x, Whh);
    k_attn<<<dim3(2, B), 256, SMEM_TC>>>(battn);
    k_out<<<dim3(2, B), 256, SMEM_TC>>>(Wfc, bfc, out);
}

// round 17
// speedup vs baseline: 1.0131x; 1.0131x over previous
#include <cuda_runtime.h>
#include <cuda_bf16.h>
#include <cuda_fp16.h>
#include <math.h>
#include <cstdint>

#define B 128
#define S 1024
#define H 256
#define V 256

// Scratch (device globals: allocation-free rule)
__device__ __half g_hhi[(size_t)B * S * H];   // hidden states, fp16 hi
__device__ float g_table[V * H];
__device__ float g_context[B * H];
__device__ __half g_wah[H * H];   // Wattn fp16
__device__ __half g_wfh[V * H];   // Wfc   fp16

typedef unsigned long long ull;

#define SWZ(o) ((o) ^ (((o) >> 3) & 0x70))

// ---- packed f32x2 helpers (k_rnn) ------------------------------------------
__device__ __forceinline__ ull fma2(ull a, ull b, ull c) {
    ull d;
    asm("fma.rn.f32x2 %0, %1, %2, %3;" : "=l"(d) : "l"(a), "l"(b), "l"(c));
    return d;
}
__device__ __forceinline__ float2 unpk(ull v) {
    float2 r;
    asm("mov.b64 {%0, %1}, %2;" : "=f"(r.x), "=f"(r.y) : "l"(v));
    return r;
}
__device__ __forceinline__ float tanhfast(float x) {
    float y;
    asm("tanh.approx.f32 %0, %1;" : "=f"(y) : "f"(x));
    return y;
}
__device__ __forceinline__ float hsum2(ull a, ull b) {
    float2 u = unpk(a), v = unpk(b);
    return (u.x + u.y) + (v.x + v.y);
}
__device__ __forceinline__ uint32_t smem_u32(const void* p) {
    uint32_t a;
    asm("{ .reg .u64 t; cvta.to.shared.u64 t, %1; cvt.u32.u64 %0, t; }"
        : "=r"(a) : "l"(p));
    return a;
}

// ---- sm80-class tensor ops --------------------------------------------------
#define LDSM4(r, a)                                                           \
    asm volatile("ldmatrix.sync.aligned.m8n8.x4.shared.b16 {%0,%1,%2,%3}, [%4];" \
        : "=r"((r)[0]), "=r"((r)[1]), "=r"((r)[2]), "=r"((r)[3]) : "r"(a))

#define MMA(d, a, bb)                                                         \
    asm volatile("mma.sync.aligned.m16n8k16.row.col.f32.f16.f16.f32 "         \
        "{%0,%1,%2,%3},{%4,%5,%6,%7},{%8,%9},{%0,%1,%2,%3};"                  \
        : "+f"((d)[0]), "+f"((d)[1]), "+f"((d)[2]), "+f"((d)[3])              \
        : "r"((a)[0]), "r"((a)[1]), "r"((a)[2]), "r"((a)[3]),                 \
          "r"((bb)[0]), "r"((bb)[1]))

// ---------------------------------------------------------------------------
// K1: table[v][j] = bxh[j] + bhh[j] + embed[v,:]·Wxh[j,:]
//     + fused fp32->fp16 conversion of Wattn/Wfc.
// ---------------------------------------------------------------------------
__global__ void k_table(const float* __restrict__ embed,
                        const float* __restrict__ Wxh,
                        const float* __restrict__ bxh,
                        const float* __restrict__ bhh,
                        const float* __restrict__ Wa,
                        const float* __restrict__ Wf,
                        __half* __restrict__ ha, __half* __restrict__ hf) {
    int v = blockIdx.x, j = threadIdx.x;
    int i = v * 256 + j;
    ha[i] = __float2half_rn(Wa[i]);
    hf[i] = __float2half_rn(Wf[i]);

    __shared__ float es[H];
    es[j] = embed[v * H + j];
    __syncthreads();
    float a0 = bxh[j] + bhh[j], a1 = 0.f, a2 = 0.f, a3 = 0.f;
    const float4* w4 = (const float4*)(Wxh + j * H);
    const float4* e4 = (const float4*)es;
    #pragma unroll
    for (int k = 0; k < H / 4; k++) {
        float4 w = w4[k], e = e4[k];
        a0 += w.x * e.x; a1 += w.y * e.y; a2 += w.z * e.z; a3 += w.w * e.w;
    }
    g_table[v * H + j] = (a0 + a1) + (a2 + a3);
}

// ---------------------------------------------------------------------------
// K2: Elman recurrence — frozen proven design; fp16-hi store.
// Token-dtype detection folded in: all CTAs scan the (always in-bounds)
// first 8KB prefix; int64 => all odd 32-bit words are zero.
// ---------------------------------------------------------------------------
#define KREG 192
#define KSMG 16
#define SMEM_RNN (KSMG * 256 * 16 + 2 * 256 * 4)

__global__ void __launch_bounds__(256, 1)
k_rnn(const void* __restrict__ xraw, const float* __restrict__ Whh) {
    extern __shared__ char smraw[];
    ulonglong2* ws = (ulonglong2*)smraw;
    float* hsm = (float*)(smraw + KSMG * 256 * 16);
    __shared__ unsigned det;

    int tid = threadIdx.x, b = blockIdx.x;
    if (tid == 0) det = 0u;

    unsigned accd = 0;
    {
        const unsigned* xw = (const unsigned*)xraw;
        #pragma unroll
        for (int i = 0; i < 4; i++) accd |= xw[2 * (tid + 256 * i) + 1];
    }

    for (int i = tid; i < KSMG * 256; i += 256) {
        int j = i & 255, g = i >> 8;
        ws[i] = *(const ulonglong2*)(Whh + j * H + KREG + 4 * g);
    }
    ull w[96];
    {
        const ulonglong2* p = (const ulonglong2*)(Whh + tid * H);
        #pragma unroll
        for (int i = 0; i < 48; i++) {
            ulonglong2 v = p[i];
            w[2 * i] = v.x; w[2 * i + 1] = v.y;
        }
    }
    hsm[tid] = 0.f;
    __syncthreads();
    if (accd) atomicOr(&det, 1u);
    __syncthreads();

    int is64 = (det == 0u);
    const long long* x64 = (const long long*)xraw;
    const int*       x32 = (const int*)xraw;

    int tok0 = is64 ? (int)x64[(size_t)b * S] : x32[b * S];
    float tv = g_table[tok0 * H + tid];
    int tokn = is64 ? (int)x64[(size_t)b * S + 1] : x32[b * S + 1];
    __half* hp = g_hhi + (size_t)b * S * H + tid;

    for (int t = 0; t < S; t++) {
        float tvn = (t + 1 < S) ? g_table[tokn * H + tid] : 0.f;
        int tokn2 = (t + 2 < S)
                    ? (is64 ? (int)x64[(size_t)b * S + t + 2] : x32[b * S + t + 2])
                    : 0;

        const ulonglong2* h2 = (const ulonglong2*)(hsm + ((t & 1) << 8));
        ull a0 = 0ull, a1 = 0ull, a2 = 0ull, a3 = 0ull;
        #pragma unroll
        for (int i = 0; i < 48; i++) {
            ulonglong2 hh = h2[i];
            a0 = fma2(w[2 * i],     hh.x, a0);
            a1 = fma2(w[2 * i + 1], hh.y, a1);
        }
        #pragma unroll
        for (int g = 0; g < KSMG; g++) {
            ulonglong2 hv = h2[48 + g];
            ulonglong2 wv = ws[(g << 8) + tid];
            a2 = fma2(wv.x, hv.x, a2);
            a3 = fma2(wv.y, hv.y, a3);
        }
        float s = hsum2(a0, a1) + hsum2(a2, a3) + tv;
        float hn = tanhfast(s);

        hsm[(((t & 1) ^ 1) << 8) + tid] = hn;
        hp[(size_t)t * H] = __float2half_rn(hn);
        tv = tvn; tokn = tokn2;
        __syncthreads();
    }
}

// ---------------------------------------------------------------------------
// HMMA GEMM v2, occ 2. CTA = 128 rows x 64 s, K=256, 8 warps (4j x 2s),
// warp tile 32 rows x 32 s, acc = 32 fp32/thread. 64 iters (16 s-blocks x 4
// k-chunks). SMEM: A [0,64K) 4 chunks x [128r][64k] SW128; B 2 x 8KB at 64K;
// scratch at 80K.
// ---------------------------------------------------------------------------
#define SMB 65536
#define SMBUF 8192
#define SMSCR 81920
#define SMEM_ATT (SMSCR + 128 * 9 * 2 * 4)    // 91136
#define SMEM_OUT (SMSCR + 2560)               // 84480

__device__ __forceinline__ void stage_A(char* smA,
                                        const __half* __restrict__ W,
                                        int tid) {
    #pragma unroll
    for (int it = 0; it < 16; it++) {
        int idx = it * 256 + tid;
        int j = idx >> 5, kg = idx & 31;
        uint4 v = *(const uint4*)(W + ((size_t)j << 8) + (kg << 3));
        int c = kg >> 3;
        int kb = (kg & 7) << 4;
        *(uint4*)(smA + c * 16384 + SWZ(j * 128 + kb)) = v;
    }
}

// B chunk = 64 s x 64 k fp16 = 8KB. Thread: row s = tid>>2, 32B slice.
__device__ __forceinline__ void ldgB(uint4* v, const __half* __restrict__ rb,
                                     int tid) {
    int s = tid >> 2, sl = (tid & 3) * 16;
    const uint4* src = (const uint4*)(rb + (size_t)s * H + sl);
    v[0] = src[0]; v[1] = src[1];
}
__device__ __forceinline__ void stsB(char* smB, const uint4* v, int tid) {
    int s = tid >> 2, sl = (tid & 3) * 32;
    *(uint4*)(smB + SWZ(s * 128 + sl)) = v[0];
    *(uint4*)(smB + SWZ(s * 128 + sl + 16)) = v[1];
}

// One K=64 chunk: 16 LDSM + 32 HMMA into 32 fp32 acc (32j x 32s per warp).
__device__ __forceinline__ void mma_chunk(float* acc, uint32_t aB, uint32_t bB,
                                          int cchunk, int wj, int ws, int lane) {
    int r = lane & 7, g = lane >> 3;
    #pragma unroll
    for (int kt = 0; kt < 4; kt++) {
        unsigned ah[2][4];
        #pragma unroll
        for (int mt = 0; mt < 2; mt++) {
            int row = wj * 32 + mt * 16 + (g & 1) * 8 + r;
            LDSM4(ah[mt], aB + cchunk * 16384 +
                          SWZ(row * 128 + kt * 32 + (g >> 1) * 16));
        }
        unsigned bh[2][4];
        #pragma unroll
        for (int pr = 0; pr < 2; pr++) {
            int srow = ws * 32 + pr * 16 + (g >> 1) * 8 + r;
            LDSM4(bh[pr], bB + SWZ(srow * 128 + kt * 32 + (g & 1) * 16));
        }
        #pragma unroll
        for (int mt = 0; mt < 2; mt++)
            #pragma unroll
            for (int nt = 0; nt < 4; nt++) {
                float* d = acc + (mt * 4 + nt) * 4;
                unsigned* bhp = &bh[nt >> 1][(nt & 1) * 2];
                MMA(d, ah[mt], bhp);
            }
    }
}

// ---------------------------------------------------------------------------
// K3: scores GEMM + no-max softmax + context. Grid (2, B), 256 thr, occ 2.
// Scatter epilogue; hj from L2-resident g_hhi.
// ---------------------------------------------------------------------------
__global__ void __launch_bounds__(256, 2)
k_attn(const float* __restrict__ battn) {
    extern __shared__ char sm[];
    uint32_t sb = smem_u32(sm);
    int tid = threadIdx.x, lane = tid & 31, w = tid >> 5;
    int wj = w >> 1, ws = w & 1;
    int mrow = lane >> 2, c2 = (lane & 3) * 2;
    int b = blockIdx.y, jbase = blockIdx.x * 128;

    stage_A(sm, g_wah + (size_t)jbase * H, tid);

    const __half* hhi = g_hhi + (size_t)b * S * H;

    float bb[4], li[4], ci[4];
    #pragma unroll
    for (int mt = 0; mt < 2; mt++)
        #pragma unroll
        for (int rr = 0; rr < 2; rr++) {
            int si = mt * 2 + rr;
            bb[si] = battn[jbase + wj * 32 + mt * 16 + rr * 8 + mrow];
            li[si] = 0.f; ci[si] = 0.f;
        }

    float acc[32];
    #pragma unroll
    for (int i = 0; i < 32; i++) acc[i] = 0.f;

    {
        uint4 v0[2];
        ldgB(v0, hhi, tid);
        stsB(sm + SMB, v0, tid);
    }
    __syncthreads();

    for (int q = 0; q < 64; q++) {
        uint4 nv[2];
        if (q < 63)
            ldgB(nv, hhi + (size_t)((q + 1) >> 2) * 64 * H + ((q + 1) & 3) * 64,
                 tid);
        mma_chunk(acc, sb, sb + SMB + (q & 1) * SMBUF, q & 3, wj, ws, lane);

        if ((q & 3) == 3) {
            int sblk = q >> 2;
            #pragma unroll
            for (int mt = 0; mt < 2; mt++)
                #pragma unroll
                for (int rr = 0; rr < 2; rr++) {
                    int si = mt * 2 + rr;
                    int jg = jbase + wj * 32 + mt * 16 + rr * 8 + mrow;
                    #pragma unroll
                    for (int nt = 0; nt < 4; nt++)
                        #pragma unroll
                        for (int col = 0; col < 2; col++) {
                            int sg = sblk * 64 + ws * 32 + nt * 8 + c2 + col;
                            float sc = acc[(mt * 4 + nt) * 4 + 2 * rr + col]
                                       + bb[si];
                            float p = __expf(sc);
                            float hj = __half2float(hhi[(size_t)sg * H + jg]);
                            li[si] += p; ci[si] += p * hj;
                        }
                }
            #pragma unroll
            for (int i = 0; i < 32; i++) acc[i] = 0.f;
        }
        if (q < 63)
            stsB(sm + SMB + ((q + 1) & 1) * SMBUF, nv, tid);
        __syncthreads();
    }

    // merge 8 partials per j (2 ws x 4 c2-lane-groups)
    float* Ml = (float*)(sm + SMSCR);
    float* Mc = Ml + 128 * 9;
    int p8 = ws * 4 + (lane & 3);
    #pragma unroll
    for (int mt = 0; mt < 2; mt++)
        #pragma unroll
        for (int rr = 0; rr < 2; rr++) {
            int jl = wj * 32 + mt * 16 + rr * 8 + mrow;
            int si = mt * 2 + rr;
            Ml[jl * 9 + p8] = li[si];
            Mc[jl * 9 + p8] = ci[si];
        }
    __syncthreads();
    if (tid < 128) {
        float L = 0.f, C = 0.f;
        #pragma unroll
        for (int p = 0; p < 8; p++) {
            L += Ml[tid * 9 + p];
            C += Mc[tid * 9 + p];
        }
        g_context[b * H + jbase + tid] = C / L;
    }
}

// ---------------------------------------------------------------------------
// K4: output GEMM. Grid (2, B), 256 thr, occ 2. Ctxout in prologue;
// scatter-store epilogue.
// ---------------------------------------------------------------------------
__global__ void __launch_bounds__(256, 2)
k_out(const float* __restrict__ Wfc, const float* __restrict__ bfc,
      float* __restrict__ out) {
    extern __shared__ char sm[];
    uint32_t sb = smem_u32(sm);
    int tid = threadIdx.x, lane = tid & 31, w = tid >> 5;
    int wj = w >> 1, ws = w & 1;
    int mrow = lane >> 2, c2 = (lane & 3) * 2;
    int b = blockIdx.y, vbase = blockIdx.x * 128;

    stage_A(sm, g_wfh + (size_t)vbase * H, tid);

    const __half* hhi = g_hhi + (size_t)b * S * H;
    float* ob = out + (size_t)b * S * V;

    // prologue: ctxout for this CTA's 128 v
    float* ctx  = (float*)(sm + SMSCR);   // 256
    float* psum = ctx + 256;              // 256
    float* ctxo = ctx + 512;              // 128
    ctx[tid] = g_context[b * H + tid];
    __syncthreads();
    {
        int vloc = tid >> 1, hf = tid & 1;
        const float4* wr = (const float4*)(Wfc + (size_t)(vbase + vloc) * H +
                                           hf * 128);
        const float4* c4 = (const float4*)(ctx + hf * 128);
        float a0 = 0.f, a1 = 0.f, a2 = 0.f, a3 = 0.f;
        #pragma unroll
        for (int i = 0; i < 32; i++) {
            float4 ww = wr[i], cc = c4[i];
            a0 += ww.x * cc.x; a1 += ww.y * cc.y;
            a2 += ww.z * cc.z; a3 += ww.w * cc.w;
        }
        psum[tid] = (a0 + a1) + (a2 + a3);
    }
    __syncthreads();
    if (tid < 128) ctxo[tid] = bfc[vbase + tid] + psum[2 * tid] + psum[2 * tid + 1];
    __syncthreads();
    float cv[4];
    #pragma unroll
    for (int mt = 0; mt < 2; mt++) {
        cv[mt * 2]     = ctxo[wj * 32 + mt * 16 + mrow];
        cv[mt * 2 + 1] = ctxo[wj * 32 + mt * 16 + mrow + 8];
    }
    __syncthreads();

    float acc[32];
    #pragma unroll
    for (int i = 0; i < 32; i++) acc[i] = 0.f;

    {
        uint4 v0[2];
        ldgB(v0, hhi, tid);
        stsB(sm + SMB, v0, tid);
    }
    __syncthreads();

    for (int q = 0; q < 64; q++) {
        uint4 nv[2];
        if (q < 63)
            ldgB(nv, hhi + (size_t)((q + 1) >> 2) * 64 * H + ((q + 1) & 3) * 64,
                 tid);
        mma_chunk(acc, sb, sb + SMB + (q & 1) * SMBUF, q & 3, wj, ws, lane);

        if ((q & 3) == 3) {
            int sblk = q >> 2;
            #pragma unroll
            for (int mt = 0; mt < 2; mt++)
                #pragma unroll
                for (int nt = 0; nt < 4; nt++) {
                    int s0 = sblk * 64 + ws * 32 + nt * 8 + c2;
                    int v0 = vbase + wj * 32 + mt * 16 + mrow;
                    const float* d = acc + (mt * 4 + nt) * 4;
                    ob[(size_t)s0 * V + v0]           = d[0] + cv[mt * 2];
                    ob[(size_t)(s0 + 1) * V + v0]     = d[1] + cv[mt * 2];
                    ob[(size_t)s0 * V + v0 + 8]       = d[2] + cv[mt * 2 + 1];
                    ob[(size_t)(s0 + 1) * V + v0 + 8] = d[3] + cv[mt * 2 + 1];
                }
            #pragma unroll
            for (int i = 0; i < 32; i++) acc[i] = 0.f;
        }
        if (q < 63)
            stsB(sm + SMB + ((q + 1) & 1) * SMBUF, nv, tid);
        __syncthreads();
    }
}

// ---------------------------------------------------------------------------
extern "C" void kernel_launch(void* const* d_in, const int* in_sizes, int n_in,
                              void* d_out, int out_size) {
    const void*  x     = d_in[0];
    const float* embed = (const float*)d_in[1];
    const float* Wxh   = (const float*)d_in[2];
    const float* bxh   = (const float*)d_in[3];
    const float* Whh   = (const float*)d_in[4];
    const float* bhh   = (const float*)d_in[5];
    const float* Wattn = (const float*)d_in[6];
    const float* battn = (const float*)d_in[7];
    const float* Wfc   = (const float*)d_in[8];
    const float* bfc   = (const float*)d_in[9];
    float* out = (float*)d_out;

    cudaFuncSetAttribute(k_rnn, cudaFuncAttributeMaxDynamicSharedMemorySize,
                         SMEM_RNN);
    cudaFuncSetAttribute(k_attn, cudaFuncAttributeMaxDynamicSharedMemorySize,
                         SMEM_ATT);
    cudaFuncSetAttribute(k_out, cudaFuncAttributeMaxDynamicSharedMemorySize,
                         SMEM_OUT);

    __half *wah, *wfh;
    cudaGetSymbolAddress((void**)&wah, g_wah);
    cudaGetSymbolAddress((void**)&wfh, g_wfh);

    k_table<<<V, H>>>(embed, Wxh, bxh, bhh, Wattn, Wfc, wah, wfh);
    k_rnn<<<B, 256, SMEM_RNN>>>(x, Whh);
    k_attn<<<dim3(2, B), 256, SMEM_ATT>>>(battn);
    k_out<<<dim3(2, B), 256, SMEM_OUT>>>(Wfc, bfc, out);
}